// round 9
// baseline (speedup 1.0000x reference)
#include <cuda_runtime.h>
#include <math.h>
#include <float.h>
#include <stdint.h>

// ---------------- problem constants ----------------
// BT=192, NQ=64, NC=1024, C=384, H=8, DH=48, HID=1536
#define QROWS   12288      /* BT*NQ            */
#define CROWS   196608     /* BT*NC            */
#define CDIM    384
#define HEADS   8
#define DHEAD   48
#define HIDDEN  1536
#define ATT_SCALE 0.14433756729740643f  /* 48^-0.5 */

// ---------------- scratch (device globals; no allocations allowed) -------
__device__ float g_xn [QROWS * CDIM];            //  18.9 MB
__device__ float g_cn [CROWS * CDIM];            // 302   MB
__device__ float g_q  [QROWS * CDIM];            //  18.9 MB
__device__ float g_kv [CROWS * 2 * CDIM];        // 604   MB
__device__ float g_o  [QROWS * CDIM];            //  18.9 MB
__device__ float g_xn2[QROWS * CDIM];            //  18.9 MB
__device__ float g_h  [QROWS * HIDDEN];          //  75.5 MB
__device__ int   g_mask_is_u8;                   // mask dtype flag

// ---------------- mask dtype detection ----------------
__global__ void detect_mask_kernel(const unsigned char* __restrict__ m)
{
    __shared__ int any;
    if (threadIdx.x == 0) any = 0;
    __syncthreads();
    int local = 0;
    for (int i = threadIdx.x; i < QROWS / 4; i += blockDim.x)
        if (m[4 * i + 1]) local = 1;
    if (local) atomicOr(&any, 1);
    __syncthreads();
    if (threadIdx.x == 0) g_mask_is_u8 = any;
}

// ---------------- LayerNorm over 384 cols, 1 block/row ----------------
__global__ __launch_bounds__(128) void ln384_kernel(
    const float* __restrict__ in, float* __restrict__ out,
    const float* __restrict__ gamma, const float* __restrict__ beta, float eps)
{
    size_t row = blockIdx.x;
    int t = threadIdx.x;
    const float* p = in + row * CDIM;
    float v0 = p[t], v1 = p[t + 128], v2 = p[t + 256];
    float s = v0 + v1 + v2;

    __shared__ float red[4];
    int lane = t & 31, warp = t >> 5;
    #pragma unroll
    for (int o = 16; o > 0; o >>= 1) s += __shfl_xor_sync(0xffffffffu, s, o);
    if (lane == 0) red[warp] = s;
    __syncthreads();
    float mean = (red[0] + red[1] + red[2] + red[3]) * (1.0f / 384.0f);

    float d0 = v0 - mean, d1 = v1 - mean, d2 = v2 - mean;
    float q = d0 * d0 + d1 * d1 + d2 * d2;
    #pragma unroll
    for (int o = 16; o > 0; o >>= 1) q += __shfl_xor_sync(0xffffffffu, q, o);
    __syncthreads();
    if (lane == 0) red[warp] = q;
    __syncthreads();
    float var = (red[0] + red[1] + red[2] + red[3]) * (1.0f / 384.0f);
    float rstd = rsqrtf(var + eps);

    float* po = out + row * CDIM;
    if (gamma) {
        po[t]       = d0 * rstd * gamma[t]       + beta[t];
        po[t + 128] = d1 * rstd * gamma[t + 128] + beta[t + 128];
        po[t + 256] = d2 * rstd * gamma[t + 256] + beta[t + 256];
    } else {
        po[t]       = d0 * rstd;
        po[t + 128] = d1 * rstd;
        po[t + 256] = d2 * rstd;
    }
}

// ---------------- GELU (tanh approx) ----------------
__device__ __forceinline__ float gelu_tanh(float x)
{
    float u = 0.7978845608028654f * (x + 0.044715f * x * x * x);
    return 0.5f * x * (1.0f + tanhf(u));
}

// ---------------- tf32 helpers ----------------
__device__ __forceinline__ uint32_t f2tf32(float x)
{
    uint32_t r;
    asm("cvt.rna.tf32.f32 %0, %1;" : "=r"(r) : "f"(x));
    return r;
}
// split x into (big, small), both tf32-rounded, stored as float bit patterns
__device__ __forceinline__ float2 tf32_split(float x)
{
    uint32_t bu = f2tf32(x);
    float bf = __uint_as_float(bu);
    uint32_t su = f2tf32(x - bf);
    return make_float2(bf, __uint_as_float(su));
}

__device__ __forceinline__ void mma_tf32(
    float& c0, float& c1, float& c2, float& c3,
    uint32_t a0, uint32_t a1, uint32_t a2, uint32_t a3,
    uint32_t b0, uint32_t b1)
{
    asm volatile(
        "mma.sync.aligned.m16n8k8.row.col.f32.tf32.tf32.f32 "
        "{%0,%1,%2,%3}, {%4,%5,%6,%7}, {%8,%9}, {%0,%1,%2,%3};"
        : "+f"(c0), "+f"(c1), "+f"(c2), "+f"(c3)
        : "r"(a0), "r"(a1), "r"(a2), "r"(a3), "r"(b0), "r"(b1));
}

// ---------------- 3xTF32 tensor-core GEMM ----------------
// C(MxN) = A(MxK) @ B(KxN) + bias [+gelu | +res]
// 128x128 block tile, KTILE=16, 256 threads = 8 warps (4 along M x 2 along N),
// warp tile 32x64 via m16n8k8. A,B fp32 in gmem; split to (big,small) float2
// in smem on load. 3 mma passes: Ab*Bb + Ab*Bs + As*Bb.
// EPI: 0 = bias, 1 = bias+gelu, 2 = bias+residual
#define KTILE 16
#define APAD  18   /* f2 stride for As row: even -> 16B-aligned rows */
#define BPAD  130  /* f2 stride for Bs row */

template <int EPI>
__global__ __launch_bounds__(256) void gemm_tc_kernel(
    const float* __restrict__ A, const float* __restrict__ B,
    const float* __restrict__ bias, const float* __restrict__ res,
    float* __restrict__ Cm, int M, int N, int K)
{
    __shared__ float2 As[128][APAD];
    __shared__ float2 Bs[KTILE][BPAD];

    int t  = threadIdx.x;
    int m0 = blockIdx.y * 128, n0 = blockIdx.x * 128;
    int wid = t >> 5, lane = t & 31;
    int wm = wid & 3, wn = wid >> 2;           // warp grid 4x2
    int group = lane >> 2, lane4 = lane & 3;

    // G->S assignments
    int ar = t >> 1,  ac = (t & 1) * 8;        // A: 128 rows x 16 cols, 2 thr/row
    int br = t >> 4,  bc = (t & 15) * 8;       // B: 16 rows x 128 cols, 16 thr/row

    float acc[2][8][4];
    #pragma unroll
    for (int mt = 0; mt < 2; mt++)
        #pragma unroll
        for (int nt = 0; nt < 8; nt++)
            #pragma unroll
            for (int r = 0; r < 4; r++) acc[mt][nt][r] = 0.0f;

    const float* Arow = A + (size_t)(m0 + ar) * K + ac;
    const float* Brow = B + (size_t)br * N + n0 + bc;

    for (int k0 = 0; k0 < K; k0 += KTILE) {
        // load + split A tile
        float4 a4a = *(const float4*)(Arow + k0);
        float4 a4b = *(const float4*)(Arow + k0 + 4);
        As[ar][ac + 0] = tf32_split(a4a.x);
        As[ar][ac + 1] = tf32_split(a4a.y);
        As[ar][ac + 2] = tf32_split(a4a.z);
        As[ar][ac + 3] = tf32_split(a4a.w);
        As[ar][ac + 4] = tf32_split(a4b.x);
        As[ar][ac + 5] = tf32_split(a4b.y);
        As[ar][ac + 6] = tf32_split(a4b.z);
        As[ar][ac + 7] = tf32_split(a4b.w);
        // load + split B tile
        float4 b4a = *(const float4*)(Brow + (size_t)k0 * N);
        float4 b4b = *(const float4*)(Brow + (size_t)k0 * N + 4);
        Bs[br][bc + 0] = tf32_split(b4a.x);
        Bs[br][bc + 1] = tf32_split(b4a.y);
        Bs[br][bc + 2] = tf32_split(b4a.z);
        Bs[br][bc + 3] = tf32_split(b4a.w);
        Bs[br][bc + 4] = tf32_split(b4b.x);
        Bs[br][bc + 5] = tf32_split(b4b.y);
        Bs[br][bc + 6] = tf32_split(b4b.z);
        Bs[br][bc + 7] = tf32_split(b4b.w);
        __syncthreads();

        #pragma unroll
        for (int kk = 0; kk < KTILE / 8; kk++) {
            int k8 = kk * 8;
            // A fragments (2 m16 tiles)
            float2 af[2][4];
            #pragma unroll
            for (int mt = 0; mt < 2; mt++) {
                int r0 = wm * 32 + mt * 16 + group;
                af[mt][0] = As[r0    ][k8 + lane4];
                af[mt][1] = As[r0 + 8][k8 + lane4];
                af[mt][2] = As[r0    ][k8 + lane4 + 4];
                af[mt][3] = As[r0 + 8][k8 + lane4 + 4];
            }
            #pragma unroll
            for (int nt = 0; nt < 8; nt++) {
                int c = wn * 64 + nt * 8 + group;
                float2 bf0 = Bs[k8 + lane4    ][c];
                float2 bf1 = Bs[k8 + lane4 + 4][c];
                uint32_t bb0 = __float_as_uint(bf0.x);
                uint32_t bb1 = __float_as_uint(bf1.x);
                uint32_t bs0 = __float_as_uint(bf0.y);
                uint32_t bs1 = __float_as_uint(bf1.y);
                #pragma unroll
                for (int mt = 0; mt < 2; mt++) {
                    uint32_t ab0 = __float_as_uint(af[mt][0].x);
                    uint32_t ab1 = __float_as_uint(af[mt][1].x);
                    uint32_t ab2 = __float_as_uint(af[mt][2].x);
                    uint32_t ab3 = __float_as_uint(af[mt][3].x);
                    float* c4 = acc[mt][nt];
                    mma_tf32(c4[0], c4[1], c4[2], c4[3], ab0, ab1, ab2, ab3, bb0, bb1);
                    mma_tf32(c4[0], c4[1], c4[2], c4[3], ab0, ab1, ab2, ab3, bs0, bs1);
                    mma_tf32(c4[0], c4[1], c4[2], c4[3],
                             __float_as_uint(af[mt][0].y), __float_as_uint(af[mt][1].y),
                             __float_as_uint(af[mt][2].y), __float_as_uint(af[mt][3].y),
                             bb0, bb1);
                }
            }
        }
        __syncthreads();
    }

    // epilogue
    #pragma unroll
    for (int mt = 0; mt < 2; mt++) {
        int row0 = m0 + wm * 32 + mt * 16 + group;
        #pragma unroll
        for (int nt = 0; nt < 8; nt++) {
            int col = n0 + wn * 64 + nt * 8 + lane4 * 2;
            float b0 = bias[col], b1 = bias[col + 1];
            float v0 = acc[mt][nt][0] + b0;
            float v1 = acc[mt][nt][1] + b1;
            float v2 = acc[mt][nt][2] + b0;
            float v3 = acc[mt][nt][3] + b1;
            if (EPI == 1) {
                v0 = gelu_tanh(v0); v1 = gelu_tanh(v1);
                v2 = gelu_tanh(v2); v3 = gelu_tanh(v3);
            }
            if (EPI == 2) {
                size_t i0 = (size_t)row0 * N + col;
                size_t i1 = (size_t)(row0 + 8) * N + col;
                v0 += res[i0]; v1 += res[i0 + 1];
                v2 += res[i1]; v3 += res[i1 + 1];
            }
            *(float2*)&Cm[(size_t)row0 * N + col]       = make_float2(v0, v1);
            *(float2*)&Cm[(size_t)(row0 + 8) * N + col] = make_float2(v2, v3);
        }
    }
}

// ---------------- flash attention: 1 block per (b, h) ----------------
__global__ __launch_bounds__(256) void attn_kernel(
    const float* __restrict__ q, const float* __restrict__ kv,
    const void* __restrict__ mask, float* __restrict__ o)
{
    int b = blockIdx.x >> 3;   // / HEADS
    int h = blockIdx.x & 7;
    int t = threadIdx.x;

    __shared__ float qs[64][48];
    __shared__ float ks[32][48];
    __shared__ float vs[32][48];
    __shared__ float ss[64][32];

    #pragma unroll
    for (int i = 0; i < 12; i++) {              // 64*48 = 3072 = 256*12
        int idx = t + i * 256;
        int qi = idx / 48, d = idx % 48;
        qs[qi][d] = q[(size_t)(b * 64 + qi) * CDIM + h * 48 + d] * ATT_SCALE;
    }
    __syncthreads();

    int qi    = t >> 2;
    int quad  = t & 3;
    int dbase = quad * 12;

    bool keep;
    {
        int mi = b * 64 + qi;
        if (g_mask_is_u8) keep = ((const unsigned char*)mask)[mi] != 0;
        else              keep = ((const int*)mask)[mi] != 0;
    }

    float qreg[48];
    #pragma unroll
    for (int d = 0; d < 48; d++) qreg[d] = qs[qi][d];

    float mcur = -INFINITY, l = 0.0f;
    float acc[12];
    #pragma unroll
    for (int d = 0; d < 12; d++) acc[d] = 0.0f;

    for (int kt = 0; kt < 32; kt++) {
        int k0 = kt * 32;
        __syncthreads();
        #pragma unroll
        for (int i = 0; i < 6; i++) {           // 32*48 = 1536 = 256*6
            int idx = t + i * 256;
            int ki = idx / 48, d = idx % 48;
            size_t base = (size_t)(b * 1024 + k0 + ki) * 768 + h * 48 + d;
            ks[ki][d] = kv[base];
            vs[ki][d] = kv[base + 384];
        }
        __syncthreads();

        int kb = quad * 8;
        #pragma unroll
        for (int j = 0; j < 8; j++) {
            float dot = 0.0f;
            #pragma unroll
            for (int d = 0; d < 48; d++) dot += qreg[d] * ks[kb + j][d];
            ss[qi][kb + j] = dot;
        }
        __syncthreads();

        float mt;
        if (keep) {
            mt = -INFINITY;
            #pragma unroll
            for (int ki = 0; ki < 32; ki++) mt = fmaxf(mt, ss[qi][ki]);
        } else {
            mt = 0.0f;
        }
        float mnew = fmaxf(mcur, mt);
        float corr = __expf(mcur - mnew);
        l *= corr;
        #pragma unroll
        for (int d = 0; d < 12; d++) acc[d] *= corr;

        #pragma unroll
        for (int ki = 0; ki < 32; ki++) {
            float sv = keep ? ss[qi][ki] : 0.0f;
            float p = __expf(sv - mnew);
            l += p;
            #pragma unroll
            for (int d = 0; d < 12; d++) acc[d] += p * vs[ki][dbase + d];
        }
        mcur = mnew;
    }

    float rl = 1.0f / l;
    float* po = o + (size_t)(b * 64 + qi) * CDIM + h * 48 + dbase;
    #pragma unroll
    for (int d = 0; d < 12; d++) po[d] = acc[d] * rl;
}

// ---------------- launch ----------------
extern "C" void kernel_launch(void* const* d_in, const int* in_sizes, int n_in,
                              void* d_out, int out_size)
{
    const float* x    = (const float*)d_in[0];
    const float* ctx  = (const float*)d_in[1];
    const void*  mask = d_in[2];
    const float* Wq  = (const float*)d_in[3];
    const float* bq  = (const float*)d_in[4];
    const float* Wkv = (const float*)d_in[5];
    const float* bkv = (const float*)d_in[6];
    const float* Wo  = (const float*)d_in[7];
    const float* bo  = (const float*)d_in[8];
    const float* gc  = (const float*)d_in[9];
    const float* bc  = (const float*)d_in[10];
    const float* W1  = (const float*)d_in[11];
    const float* b1  = (const float*)d_in[12];
    const float* W2  = (const float*)d_in[13];
    const float* b2  = (const float*)d_in[14];
    float* out = (float*)d_out;

    float *p_xn, *p_cn, *p_q, *p_kv, *p_o, *p_xn2, *p_h;
    cudaGetSymbolAddress((void**)&p_xn,  g_xn);
    cudaGetSymbolAddress((void**)&p_cn,  g_cn);
    cudaGetSymbolAddress((void**)&p_q,   g_q);
    cudaGetSymbolAddress((void**)&p_kv,  g_kv);
    cudaGetSymbolAddress((void**)&p_o,   g_o);
    cudaGetSymbolAddress((void**)&p_xn2, g_xn2);
    cudaGetSymbolAddress((void**)&p_h,   g_h);

    // 0) mask dtype detection
    detect_mask_kernel<<<1, 256>>>((const unsigned char*)mask);

    // 1) norms
    ln384_kernel<<<QROWS, 128>>>(x,   p_xn, nullptr, nullptr, 1e-6f);
    ln384_kernel<<<CROWS, 128>>>(ctx, p_cn, gc,      bc,      1e-5f);

    // 2) projections (3xTF32 tensor cores)
    gemm_tc_kernel<0><<<dim3(CDIM / 128,     QROWS / 128), 256>>>(
        p_xn, Wq,  bq,  nullptr, p_q,  QROWS, CDIM,     CDIM);
    gemm_tc_kernel<0><<<dim3(2 * CDIM / 128, CROWS / 128), 256>>>(
        p_cn, Wkv, bkv, nullptr, p_kv, CROWS, 2 * CDIM, CDIM);

    // 3) attention
    attn_kernel<<<192 * HEADS, 256>>>(p_q, p_kv, mask, p_o);

    // 4) output projection + residual -> d_out
    gemm_tc_kernel<2><<<dim3(CDIM / 128, QROWS / 128), 256>>>(
        p_o, Wo, bo, x, out, QROWS, CDIM, CDIM);

    // 5) MLP branch
    ln384_kernel<<<QROWS, 128>>>(out, p_xn2, nullptr, nullptr, 1e-6f);
    gemm_tc_kernel<1><<<dim3(HIDDEN / 128, QROWS / 128), 256>>>(
        p_xn2, W1, b1, nullptr, p_h, QROWS, HIDDEN, CDIM);
    gemm_tc_kernel<2><<<dim3(CDIM / 128, QROWS / 128), 256>>>(
        p_h, W2, b2, out, out, QROWS, CDIM, HIDDEN);
}